// round 4
// baseline (speedup 1.0000x reference)
#include <cuda_runtime.h>

// CTC loss forward: 4-warp lockstep-epoch wavefront per batch element.
// alpha[s] = v * 2^e (v in [1,2) fp32, e int32) -> per-state unbounded range.
// CTA b = batch b, 128 threads, thread tid owns state s=tid (tid 127 also
// owns s=128). Epoch e: warp w runs time-block m=e-w (K steps). Boundary
// states (lanes 30,31 of warp w-1) flow through a 64-slot smem ring; one
// __syncthreads per epoch separates producer writes from consumer reads.

#define K_STEPS 16
#define RINGN   64
#define PF      8
#define EMIN    (-(1 << 27))

__device__ float    g_loss[1024];
__device__ unsigned g_cnt = 0;

__global__ void __launch_bounds__(128, 1)
ctc_pipe_kernel(const float* __restrict__ logp,
                const int*   __restrict__ targets,
                const int*   __restrict__ in_len,
                const int*   __restrict__ tgt_len,
                float*       __restrict__ out,
                int T, int B, int C, int S)
{
    const int b    = blockIdx.x;
    const int tid  = threadIdx.x;
    const int w    = tid >> 5;
    const int lane = tid & 31;
    const int L    = 2 * S + 1;
    const int s    = tid;
    const int* tgt = targets + (size_t)b * S;

    __shared__ float rv1[3][RINGN]; __shared__ int re1[3][RINGN]; // s=32w+31
    __shared__ float rv0[3][RINGN]; __shared__ int re0[3][RINGN]; // s=32w+30
    __shared__ float fv[130];       __shared__ int fe[130];
    __shared__ float red[4];
    __shared__ int   s_last;

    // per-thread constants
    const bool valid = (s < L);
    int lab = 0;
    if (valid && (s & 1)) lab = tgt[s >> 1];
    int skm = 0;
    if (valid && s >= 3 && (s & 1)) {
        int lm2 = tgt[(s - 2) >> 1];
        if (lab != 0 && lab != lm2) skm = ~0;
    }
    const int  emin_m = EMIN & ~skm;
    const bool xtra   = (tid == 127) && (L > 128);

    const size_t BC   = (size_t)B * C;
    const float* base = logp + (size_t)b * C;

    int len = in_len[b];
    if (len > T) len = T;
    if (len < 1) len = 1;
    const float* rowEnd = base + (size_t)(len - 1) * BC;

    // ---- init t=0 ----
    float v = 1.0f; int e = EMIN;
    if (s == 0) {
        float y = __ldg(base) * 1.4426950408889634f;
        float f0 = floorf(y); e = (int)f0; v = exp2f(y - f0);
    }
    if (s == 1 && L > 1) {
        float y = __ldg(base + lab) * 1.4426950408889634f;
        float f0 = floorf(y); e = (int)f0; v = exp2f(y - f0);
    }
    float v2 = 1.0f; int e2 = EMIN;   // state s=128 (tid 127 only)

    if (w < 3) {
        if (lane == 31) { rv1[w][0] = v; re1[w][0] = e; }
        if (lane == 30) { rv0[w][0] = v; re0[w][0] = e; }
    }

    // ---- emission prefetch (registers, PF deep) ----
    float lpb[PF], lpb2[PF];
#pragma unroll
    for (int k = 0; k < PF; ++k) {
        const float* r = base + (size_t)(1 + k) * BC;
        if (r > rowEnd) r = rowEnd;
        lpb[k] = __ldg(r + lab);
        if (xtra) lpb2[k] = __ldg(r);
    }
    const float* rowp = base + (size_t)(1 + PF) * BC;
    if (rowp > rowEnd) rowp = rowEnd;

    const int NB = (len - 1 + K_STEPS - 1) / K_STEPS;  // time blocks
    const int NE = NB + 3;                              // epochs (drain 3 warps)

    __syncthreads();

    for (int ep = 0; ep < NE; ++ep) {
        const int m = ep - w;
        if (m >= 0 && m < NB) {
            const int t0   = 1 + m * K_STEPS;
            int tend = t0 + K_STEPS; if (tend > len) tend = len;

#pragma unroll 4
            for (int t = t0; t < tend; ++t) {
                const int idx = t & (PF - 1);
                float p = __expf(lpb[idx]);
                lpb[idx] = __ldg(rowp + lab);
                float pb = 0.0f;
                if (xtra) { pb = __expf(lpb2[idx]); lpb2[idx] = __ldg(rowp); }
                rowp += BC; if (rowp > rowEnd) rowp = rowEnd;

                float vm1 = __shfl_up_sync(0xffffffffu, v, 1);
                int   em1 = __shfl_up_sync(0xffffffffu, e, 1);
                float vm2 = __shfl_up_sync(0xffffffffu, v, 2);
                int   em2 = __shfl_up_sync(0xffffffffu, e, 2);
                if (lane < 2) {
                    if (w == 0) {
                        if (lane == 0) em1 = EMIN;
                        em2 = EMIN;
                    } else {
                        const int slot = (t - 1) & (RINGN - 1);
                        float bv1 = rv1[w - 1][slot]; int be1 = re1[w - 1][slot];
                        if (lane == 0) {
                            vm1 = bv1; em1 = be1;
                            vm2 = rv0[w - 1][slot]; em2 = re0[w - 1][slot];
                        } else {
                            vm2 = bv1; em2 = be1;
                        }
                    }
                }

                // extended-range 3-term recurrence
                int ecx = (em2 & skm) | emin_m;
                int mx  = max(e, max(em1, ecx));
                int da  = max(e   - mx, -126);
                int db  = max(em1 - mx, -126);
                int dc  = max(ecx - mx, -126);
                float f = v * __int_as_float((da + 127) << 23);
                f = fmaf(vm1, __int_as_float((db + 127) << 23), f);
                f = fmaf(vm2, __int_as_float((dc + 127) << 23), f);
                f *= p;
                int bits  = __float_as_int(f);
                int ne_   = mx + ((bits >> 23) & 0xff) - 127;
                float nv_ = __int_as_float((bits & 0x007FFFFF) | 0x3F800000);

                if (xtra) {  // s=128: old a128 (v2,e2) + old a127 (v,e)
                    int m2 = max(e2, e);
                    int d1 = max(e2 - m2, -126);
                    int d2 = max(e  - m2, -126);
                    float f2 = v2 * __int_as_float((d1 + 127) << 23);
                    f2 = fmaf(v, __int_as_float((d2 + 127) << 23), f2);
                    f2 *= pb;
                    int b2 = __float_as_int(f2);
                    e2 = m2 + ((b2 >> 23) & 0xff) - 127;
                    v2 = __int_as_float((b2 & 0x007FFFFF) | 0x3F800000);
                }

                v = valid ? nv_ : 1.0f;
                e = valid ? ne_ : EMIN;

                if (w < 3) {
                    const int slot = t & (RINGN - 1);
                    if (lane == 31)      { rv1[w][slot] = v; re1[w][slot] = e; }
                    else if (lane == 30) { rv0[w][slot] = v; re0[w][slot] = e; }
                }
            }
        }
        __syncthreads();
    }

    // ---- finish: per-batch loss ----
    if (valid) { fv[s] = v; fe[s] = e; }
    if (xtra)  { fv[128] = v2; fe[128] = e2; }
    __syncthreads();
    if (tid == 0) {
        int tl = tgt_len[b];
        int hi = 2 * tl; if (hi > L - 1) hi = L - 1;
        float loss = 0.0f;
        if (tl > 0) {
            int   ea = fe[hi];                 float va = fv[hi];
            int   eb = (hi >= 1) ? fe[hi - 1] : EMIN;
            float vb = (hi >= 1) ? fv[hi - 1] : 1.0f;
            int mx = max(ea, eb);
            if (mx > EMIN / 2) {
                float sa = va * __int_as_float((max(ea - mx, -126) + 127) << 23);
                float sb = vb * __int_as_float((max(eb - mx, -126) + 127) << 23);
                double ll = ((double)mx + (double)log2f(sa + sb)) * 0.69314718055994530942;
                loss = (float)(-ll / (double)tl);
            }
        }
        g_loss[b] = loss;
        __threadfence();
        unsigned old = atomicAdd(&g_cnt, 1);
        s_last = (old == (unsigned)(gridDim.x - 1)) ? 1 : 0;
    }
    __syncthreads();

    // ---- last CTA: fused mean reduction ----
    if (s_last) {
        __threadfence();
        float acc = 0.0f;
        for (int i = tid; i < B; i += 128) acc += g_loss[i];
#pragma unroll
        for (int o = 16; o > 0; o >>= 1)
            acc += __shfl_xor_sync(0xffffffffu, acc, o);
        if (lane == 0) red[w] = acc;
        __syncthreads();
        if (tid == 0) {
            out[0] = (red[0] + red[1] + red[2] + red[3]) / (float)B;
            g_cnt = 0;   // reset for next graph replay
        }
    }
}

extern "C" void kernel_launch(void* const* d_in, const int* in_sizes, int n_in,
                              void* d_out, int out_size)
{
    const float* logp    = (const float*)d_in[0];
    const int*   targets = (const int*)d_in[1];
    const int*   in_len  = (const int*)d_in[2];
    const int*   tgt_len = (const int*)d_in[3];

    int B = in_sizes[2];                                   // 128
    int S = in_sizes[1] / B;                               // 64
    int C = 256;
    int T = (int)((size_t)in_sizes[0] / ((size_t)B * C));  // 1024

    ctc_pipe_kernel<<<B, 128>>>(logp, targets, in_len, tgt_len,
                                (float*)d_out, T, B, C, S);
}

// round 5
// speedup vs baseline: 2.5919x; 2.5919x over previous
#include <cuda_runtime.h>
#include <limits.h>

// CTC loss forward, warp-specialized: 1 compute warp + 3 loader warps per CTA.
// alpha[s] = v * 2^e (v in [1,2) fp32, e int32): per-state unbounded range.
// Loaders stream emission rows (256 classes) coalesced from GMEM, compute
// exp() for the whole row, and publish to a 32-row smem ring. The compute
// warp (5 states/lane, L=129<=160) runs the pure-ALU recurrence, gathering
// p-values from smem. No barriers on the recurrence's critical path.

#define NST   5
#define DRING 32          // ring rows (power of 2)
#define TH_BP 20          // loader may lead consumed-counter by < TH_BP rows
#define LOOKA 7           // consumer spin lookahead
#define DEPTH 3           // loader software-pipeline depth (per-loader rows)
#define EMIN  (-(1 << 27))

__device__ float    g_loss[1024];
__device__ unsigned g_cnt = 0;

__global__ void __launch_bounds__(128, 1)
ctc_ws_kernel(const float* __restrict__ logp,
              const int*   __restrict__ targets,
              const int*   __restrict__ in_len,
              const int*   __restrict__ tgt_len,
              float*       __restrict__ out,
              int T, int B, int C, int S)
{
    const int b    = blockIdx.x;
    const int tid  = threadIdx.x;
    const int w    = tid >> 5;
    const int lane = tid & 31;
    const int L    = 2 * S + 1;
    const int* tgt = targets + (size_t)b * S;

    __shared__ float        ring[DRING][256];
    __shared__ volatile int prog[3];
    __shared__ volatile int cons;
    __shared__ float        fv[NST * 32];
    __shared__ int          fe[NST * 32];
    __shared__ float        red[4];
    __shared__ int          s_last;

    const size_t BC   = (size_t)B * C;
    const float* base = logp + (size_t)b * C;

    int len = in_len[b];
    if (len > T) len = T;
    if (len < 1) len = 1;
    const int lenm1 = len - 1;

    if (tid == 0) { cons = 0; prog[0] = 0; prog[1] = 0; prog[2] = 0; }
    __syncthreads();

    if (w == 0) {
        // ================= compute warp =================
        int   l[NST], skm[NST], emin_m[NST];
        float v[NST];
        int   e[NST];
#pragma unroll
        for (int j = 0; j < NST; ++j) {
            int s = lane * NST + j;
            bool valid = (s < L);
            int lab = 0;
            if (valid && (s & 1)) lab = tgt[s >> 1];
            l[j] = lab;
            int sk = 0;
            if (valid && s >= 3 && (s & 1)) {
                int lm2 = tgt[(s - 2) >> 1];
                if (lab != 0 && lab != lm2) sk = ~0;
            }
            skm[j] = sk;
            emin_m[j] = EMIN & ~sk;
            v[j] = 1.0f;
            e[j] = EMIN;
        }
        if (lane == 0) {
            float y  = __ldg(base) * 1.4426950408889634f;
            float f0 = floorf(y); e[0] = (int)f0; v[0] = exp2f(y - f0);
            if (L > 1) {
                float y1 = __ldg(base + l[1]) * 1.4426950408889634f;
                float f1 = floorf(y1); e[1] = (int)f1; v[1] = exp2f(y1 - f1);
            }
        }

        int avail = 0;
        for (int t = 1; t <= lenm1; ++t) {
            if (avail < t) {                       // wait for loaders (rare)
                int target = t + LOOKA;
                if (target > lenm1) target = lenm1;
                do {
                    int a0 = prog[0], a1 = prog[1], a2 = prog[2];
                    avail = min(a0, min(a1, a2));
                } while (avail < target);
                __threadfence_block();
            }
            const float* row = &ring[t & (DRING - 1)][0];
            float p[NST];
#pragma unroll
            for (int j = 0; j < NST; ++j) p[j] = row[l[j]];

            float vm1 = __shfl_up_sync(0xffffffffu, v[NST - 1], 1);
            int   em1 = __shfl_up_sync(0xffffffffu, e[NST - 1], 1);
            float vm2 = __shfl_up_sync(0xffffffffu, v[NST - 2], 1);
            int   em2 = __shfl_up_sync(0xffffffffu, e[NST - 2], 1);
            if (lane == 0) { em1 = EMIN; em2 = EMIN; }

            float nv[NST]; int ne[NST];
#pragma unroll
            for (int j = 0; j < NST; ++j) {
                float vb_ = (j == 0) ? vm1 : v[j - 1];
                int   eb_ = (j == 0) ? em1 : e[j - 1];
                float vc_ = (j == 0) ? vm2 : (j == 1) ? vm1 : v[j - 2];
                int   ec_ = (j == 0) ? em2 : (j == 1) ? em1 : e[j - 2];
                int ecx = (ec_ & skm[j]) | emin_m[j];
                int m   = max(e[j], max(eb_, ecx));
                int da  = max(e[j] - m, -126);
                int db  = max(eb_  - m, -126);
                int dc  = max(ecx  - m, -126);
                float f = v[j] * __int_as_float(da * 8388608 + 1065353216);
                f = fmaf(vb_, __int_as_float(db * 8388608 + 1065353216), f);
                f = fmaf(vc_, __int_as_float(dc * 8388608 + 1065353216), f);
                f *= p[j];
                int bits = __float_as_int(f);
                ne[j] = m + ((bits >> 23) & 0xff) - 127;
                nv[j] = __int_as_float((bits & 0x007FFFFF) | 0x3F800000);
            }
#pragma unroll
            for (int j = 0; j < NST; ++j) { v[j] = nv[j]; e[j] = ne[j]; }

            if (((t & 7) == 0) && lane == 0) cons = t;   // progress publish
        }
#pragma unroll
        for (int j = 0; j < NST; ++j) {
            fv[lane * NST + j] = v[j];
            fe[lane * NST + j] = e[j];
        }
    } else {
        // ================= loader warp i (i = 0..2) =================
        const int i  = w - 1;
        const int c0 = lane * 8;
        const float* src = base + c0;

        float4 Aa[DEPTH], Ab[DEPTH];
        int tf = 1 + i;
#pragma unroll
        for (int k = 0; k < DEPTH; ++k) {
            int tt = tf; if (tt > lenm1) tt = lenm1; if (tt < 1) tt = 1;
            const float* r = src + (size_t)tt * BC;
            Aa[k] = *(const float4*)r;
            Ab[k] = *(const float4*)(r + 4);
            tf += 3;
        }
        int kk = 0, consv = 0;
        for (int t = 1 + i; t <= lenm1; t += 3) {
            while (t - consv >= TH_BP) consv = cons;     // backpressure
            float4 a = Aa[kk], q = Ab[kk];
            float* dst = &ring[t & (DRING - 1)][c0];
            ((float4*)dst)[0] = make_float4(__expf(a.x), __expf(a.y),
                                            __expf(a.z), __expf(a.w));
            ((float4*)dst)[1] = make_float4(__expf(q.x), __expf(q.y),
                                            __expf(q.z), __expf(q.w));
            __threadfence_block();
            __syncwarp();
            if (lane == 0) prog[i] = t;                  // publish row ready
            if (tf <= lenm1) {                           // refill stage kk
                const float* r = src + (size_t)tf * BC;
                Aa[kk] = *(const float4*)r;
                Ab[kk] = *(const float4*)(r + 4);
            }
            tf += 3;
            kk = (kk == DEPTH - 1) ? 0 : kk + 1;
        }
        __threadfence_block();
        __syncwarp();
        if (lane == 0) prog[i] = INT_MAX;                // done forever
    }
    __syncthreads();

    // ---- per-batch loss ----
    if (tid == 0) {
        int tl = tgt_len[b];
        int hi = 2 * tl; if (hi > L - 1) hi = L - 1;
        float loss = 0.0f;
        if (tl > 0) {
            int   ea = fe[hi];                 float va = fv[hi];
            int   eb = (hi >= 1) ? fe[hi - 1] : EMIN;
            float vb = (hi >= 1) ? fv[hi - 1] : 1.0f;
            int mx = max(ea, eb);
            if (mx > EMIN / 2) {
                float sa = va * __int_as_float((max(ea - mx, -126) + 127) << 23);
                float sb = vb * __int_as_float((max(eb - mx, -126) + 127) << 23);
                double ll = ((double)mx + (double)log2f(sa + sb)) * 0.69314718055994530942;
                loss = (float)(-ll / (double)tl);
            }
        }
        g_loss[b] = loss;
        __threadfence();
        unsigned old = atomicAdd(&g_cnt, 1);
        s_last = (old == (unsigned)(gridDim.x - 1)) ? 1 : 0;
    }
    __syncthreads();

    // ---- last CTA: fused mean reduction ----
    if (s_last) {
        __threadfence();
        float acc = 0.0f;
        for (int i2 = tid; i2 < B; i2 += 128) acc += g_loss[i2];
#pragma unroll
        for (int o = 16; o > 0; o >>= 1)
            acc += __shfl_xor_sync(0xffffffffu, acc, o);
        if (lane == 0) red[w] = acc;
        __syncthreads();
        if (tid == 0) {
            out[0] = (red[0] + red[1] + red[2] + red[3]) / (float)B;
            g_cnt = 0;   // reset for next graph replay
        }
    }
}

extern "C" void kernel_launch(void* const* d_in, const int* in_sizes, int n_in,
                              void* d_out, int out_size)
{
    const float* logp    = (const float*)d_in[0];
    const int*   targets = (const int*)d_in[1];
    const int*   in_len  = (const int*)d_in[2];
    const int*   tgt_len = (const int*)d_in[3];

    int B = in_sizes[2];                                   // 128
    int S = in_sizes[1] / B;                               // 64
    int C = 256;
    int T = (int)((size_t)in_sizes[0] / ((size_t)B * C));  // 1024

    ctc_ws_kernel<<<B, 128>>>(logp, targets, in_len, tgt_len,
                              (float*)d_out, T, B, C, S);
}

// round 6
// speedup vs baseline: 2.7365x; 1.0558x over previous
#include <cuda_runtime.h>
#include <limits.h>

// CTC loss forward, warp-specialized (1 compute + 3 loader warps per CTA),
// block-rebased extended-range arithmetic:
//   alpha[s] = u[s] * 2^Eb[s],  Eb rebased every RSTEPS=4 steps to
//   E'[s] = max(Et[s-8..s]) (exact reach of 4 steps), making the per-step
//   scale factors sb=2^{E'[s-1]-E'[s]}, sc=2^{E'[s-2]-E'[s]} constants.
// Inner step per state: 2 FMA + 2 MUL; 2 float SHFLs per step total.

#define NST    5
#define RSTEPS 4
#define RD     16          // ring rows (power of 2)
#define TH_BP  12          // loader lead bound (< RD - RSTEPS)
#define DEPTH  3           // loader LDG pipeline depth
#define SENT   (-(1 << 28))

__device__ float    g_loss[1024];
__device__ unsigned g_cnt = 0;

__global__ void __launch_bounds__(128, 1)
ctc_ws2_kernel(const float* __restrict__ logp,
               const int*   __restrict__ targets,
               const int*   __restrict__ in_len,
               const int*   __restrict__ tgt_len,
               float*       __restrict__ out,
               int T, int B, int C, int S)
{
    const int b    = blockIdx.x;
    const int tid  = threadIdx.x;
    const int w    = tid >> 5;
    const int lane = tid & 31;
    const int L    = 2 * S + 1;
    const int* tgt = targets + (size_t)b * S;

    __shared__ float        ring[RD][NST * 32];   // [row][j*32+lane]
    __shared__ float        scratch[3][256];
    __shared__ volatile int prog[3];
    __shared__ volatile int cons;
    __shared__ float        fv[NST * 32];
    __shared__ int          fe[NST * 32];
    __shared__ float        red[4];
    __shared__ int          s_last;

    const size_t BC   = (size_t)B * C;
    const float* base = logp + (size_t)b * C;

    int len = in_len[b];
    if (len > T) len = T;
    if (len < 1) len = 1;
    const int lenm1 = len - 1;

    if (tid == 0) { cons = 0; prog[0] = 0; prog[1] = 0; prog[2] = 0; }
    __syncthreads();

    if (w == 0) {
        // ================= compute warp =================
        int skm[NST];
#pragma unroll
        for (int j = 0; j < NST; ++j) {
            int s = lane * NST + j;
            int sk = 0;
            if (s < L && s >= 3 && (s & 1)) {
                int lab = tgt[s >> 1];
                int lm2 = tgt[(s - 2) >> 1];
                if (lab != 0 && lab != lm2) sk = 1;
            }
            skm[j] = sk;
        }

        float u[NST];  int Eb[NST];
#pragma unroll
        for (int j = 0; j < NST; ++j) { u[j] = 0.0f; Eb[j] = SENT; }
        if (lane == 0) {
            float y0 = __ldg(base) * 1.4426950408889634f;
            float f0 = floorf(y0); Eb[0] = (int)f0; u[0] = exp2f(y0 - f0);
            if (L > 1) {
                int lab1 = tgt[0];
                float y1 = __ldg(base + lab1) * 1.4426950408889634f;
                float f1 = floorf(y1); Eb[1] = (int)f1; u[1] = exp2f(y1 - f1);
            }
        }

        int avail = 0;
        for (int t0 = 1; t0 < len; t0 += RSTEPS) {
            // ---------- REBASE ----------
            int Et[NST]; int mb[NST];
#pragma unroll
            for (int j = 0; j < NST; ++j) {
                int bits = __float_as_int(u[j]);
                int ex   = (bits >> 23) & 0xff;
                Et[j] = (ex == 0) ? SENT : (Eb[j] + ex - 127);
                mb[j] = bits & 0x007fffff;
            }
            int P0 = Et[0];
            int P1 = max(P0, Et[1]);
            int P2 = max(P1, Et[2]);
            int P3 = max(P2, Et[3]);
            int P4 = max(P3, Et[4]);
            int S4 = Et[4];
            int S3 = max(Et[3], S4);
            int S2 = max(Et[2], S3);
            int S1 = max(Et[1], S2);
            int M_l1  = __shfl_up_sync(0xffffffffu, P4, 1); if (lane < 1) M_l1  = SENT;
            int S1_l1 = __shfl_up_sync(0xffffffffu, S1, 1); if (lane < 1) S1_l1 = SENT;
            int S2_l2 = __shfl_up_sync(0xffffffffu, S2, 2); if (lane < 2) S2_l2 = SENT;
            int S3_l2 = __shfl_up_sync(0xffffffffu, S3, 2); if (lane < 2) S3_l2 = SENT;
            int S4_l2 = __shfl_up_sync(0xffffffffu, S4, 2); if (lane < 2) S4_l2 = SENT;
            int E0 = max(max(S2_l2, M_l1), P0);
            int E1 = max(max(S3_l2, M_l1), P1);
            int E2 = max(max(S4_l2, M_l1), P2);
            int E3 = max(M_l1, P3);
            int E4 = max(S1_l1, P4);
            int En[NST] = {E0, E1, E2, E3, E4};
#pragma unroll
            for (int j = 0; j < NST; ++j) {
                int d = Et[j] - En[j];                 // <= 0
                u[j] = (d < -126 || Et[j] <= SENT) ? 0.0f
                     : __int_as_float(mb[j] | ((d + 127) << 23));
            }
            int E4_l1 = __shfl_up_sync(0xffffffffu, E4, 1); if (lane < 1) E4_l1 = SENT;
            int E3_l1 = __shfl_up_sync(0xffffffffu, E3, 1); if (lane < 1) E3_l1 = SENT;
            int Em1[NST] = {E4_l1, E0, E1, E2, E3};
            int Em2[NST] = {E3_l1, E4_l1, E0, E1, E2};
            float sb[NST], sc[NST];
#pragma unroll
            for (int j = 0; j < NST; ++j) {
                int db = min(Em1[j] - En[j], 126);
                sb[j] = (db < -126 || Em1[j] <= SENT) ? 0.0f
                      : __int_as_float((db + 127) << 23);
                int dc = min(Em2[j] - En[j], 126);
                float scv = (dc < -126 || Em2[j] <= SENT) ? 0.0f
                          : __int_as_float((dc + 127) << 23);
                sc[j] = skm[j] ? scv : 0.0f;
                Eb[j] = En[j];
            }

            // ---------- wait for emission rows ----------
            int tend = t0 + RSTEPS; if (tend > len) tend = len;
            if (avail < tend - 1) {
                do {
                    int a0 = prog[0], a1 = prog[1], a2 = prog[2];
                    avail = min(a0, min(a1, a2));
                } while (avail < tend - 1);
                __threadfence_block();
            }

            // ---------- 4 cheap steps ----------
#pragma unroll
            for (int k = 0; k < RSTEPS; ++k) {
                int t = t0 + k;
                if (t < len) {
                    const float* rp = &ring[t & (RD - 1)][0];
                    float p0 = rp[lane];
                    float p1 = rp[32 + lane];
                    float p2 = rp[64 + lane];
                    float p3 = rp[96 + lane];
                    float p4 = rp[128 + lane];
                    float vm1 = __shfl_up_sync(0xffffffffu, u[4], 1);
                    float vm2 = __shfl_up_sync(0xffffffffu, u[3], 1);
                    if (lane == 0) { vm1 = 0.0f; vm2 = 0.0f; }
                    float n0 = fmaf(vm2,  sc[0], fmaf(vm1,  sb[0], u[0])) * p0;
                    float n1 = fmaf(vm1,  sc[1], fmaf(u[0], sb[1], u[1])) * p1;
                    float n2 = fmaf(u[0], sc[2], fmaf(u[1], sb[2], u[2])) * p2;
                    float n3 = fmaf(u[1], sc[3], fmaf(u[2], sb[3], u[3])) * p3;
                    float n4 = fmaf(u[2], sc[4], fmaf(u[3], sb[4], u[4])) * p4;
                    u[0] = n0; u[1] = n1; u[2] = n2; u[3] = n3; u[4] = n4;
                }
            }
            if (lane == 0) cons = tend - 1;
        }

        // final extraction
#pragma unroll
        for (int j = 0; j < NST; ++j) {
            int bits = __float_as_int(u[j]);
            int ex   = (bits >> 23) & 0xff;
            fe[lane * NST + j] = (ex == 0) ? SENT : (Eb[j] + ex - 127);
            fv[lane * NST + j] = __int_as_float((bits & 0x007fffff) | 0x3f800000);
        }
    } else {
        // ================= loader warp i (0..2) =================
        const int i  = w - 1;
        const int c0 = lane * 8;
        const float* src = base + c0;

        int lab2[NST];
#pragma unroll
        for (int j = 0; j < NST; ++j) {
            int s = lane * NST + j;
            int lab = 0;
            if (s < L && (s & 1)) lab = tgt[s >> 1];
            lab2[j] = lab;
        }

        float4 Aa[DEPTH], Ab[DEPTH];
        int tf = 1 + i;
#pragma unroll
        for (int k = 0; k < DEPTH; ++k) {
            int tt = tf; if (tt > lenm1) tt = lenm1; if (tt < 1) tt = 1;
            const float* r = src + (size_t)tt * BC;
            Aa[k] = *(const float4*)r;
            Ab[k] = *(const float4*)(r + 4);
            tf += 3;
        }
        int kk = 0, consv = 0;
        for (int t = 1 + i; t <= lenm1; t += 3) {
            while (t - consv >= TH_BP) consv = cons;        // backpressure
            float4 a = Aa[kk], q = Ab[kk];
            float* scr = &scratch[i][c0];
            ((float4*)scr)[0] = make_float4(__expf(a.x), __expf(a.y),
                                            __expf(a.z), __expf(a.w));
            ((float4*)scr)[1] = make_float4(__expf(q.x), __expf(q.y),
                                            __expf(q.z), __expf(q.w));
            __syncwarp();
            float* dst = &ring[t & (RD - 1)][0];
#pragma unroll
            for (int j = 0; j < NST; ++j)
                dst[j * 32 + lane] = scratch[i][lab2[j]];
            __threadfence_block();
            __syncwarp();
            if (lane == 0) prog[i] = t;
            if (tf <= lenm1) {
                const float* r = src + (size_t)tf * BC;
                Aa[kk] = *(const float4*)r;
                Ab[kk] = *(const float4*)(r + 4);
            }
            tf += 3;
            kk = (kk == DEPTH - 1) ? 0 : kk + 1;
        }
        __syncwarp();
        if (lane == 0) prog[i] = INT_MAX;
    }
    __syncthreads();

    // ---- per-batch loss ----
    if (tid == 0) {
        int tl = tgt_len[b];
        int hi = 2 * tl; if (hi > L - 1) hi = L - 1;
        float loss = 0.0f;
        if (tl > 0) {
            int   ea = fe[hi];                 float va = fv[hi];
            int   eb = (hi >= 1) ? fe[hi - 1] : SENT;
            float vb = (hi >= 1) ? fv[hi - 1] : 1.0f;
            int mx = max(ea, eb);
            if (mx > SENT / 2) {
                float sa = (ea - mx < -126) ? 0.0f : va * __int_as_float((ea - mx + 127) << 23);
                float sbv = (eb - mx < -126 || eb <= SENT) ? 0.0f : vb * __int_as_float((eb - mx + 127) << 23);
                double ll = ((double)mx + (double)log2f(sa + sbv)) * 0.69314718055994530942;
                loss = (float)(-ll / (double)tl);
            }
        }
        g_loss[b] = loss;
        __threadfence();
        unsigned old = atomicAdd(&g_cnt, 1);
        s_last = (old == (unsigned)(gridDim.x - 1)) ? 1 : 0;
    }
    __syncthreads();

    // ---- last CTA: fused mean reduction ----
    if (s_last) {
        __threadfence();
        float acc = 0.0f;
        for (int i2 = tid; i2 < B; i2 += 128) acc += g_loss[i2];
#pragma unroll
        for (int o = 16; o > 0; o >>= 1)
            acc += __shfl_xor_sync(0xffffffffu, acc, o);
        if (lane == 0) red[w] = acc;
        __syncthreads();
        if (tid == 0) {
            out[0] = (red[0] + red[1] + red[2] + red[3]) / (float)B;
            g_cnt = 0;   // reset for next graph replay
        }
    }
}

extern "C" void kernel_launch(void* const* d_in, const int* in_sizes, int n_in,
                              void* d_out, int out_size)
{
    const float* logp    = (const float*)d_in[0];
    const int*   targets = (const int*)d_in[1];
    const int*   in_len  = (const int*)d_in[2];
    const int*   tgt_len = (const int*)d_in[3];

    int B = in_sizes[2];                                   // 128
    int S = in_sizes[1] / B;                               // 64
    int C = 256;
    int T = (int)((size_t)in_sizes[0] / ((size_t)B * C));  // 1024

    ctc_ws2_kernel<<<B, 128>>>(logp, targets, in_len, tgt_len,
                               (float*)d_out, T, B, C, S);
}